// round 15
// baseline (speedup 1.0000x reference)
#include <cuda_runtime.h>
#include <cuda_fp16.h>
#include <math.h>
#include <stdint.h>

#define QSCALE 0.07216878364870323f
#define L2_10K 0.41524101186092024f
typedef unsigned long long u64;

__device__ __align__(16) float g_qn[32 * 4096];
__device__ __align__(16) float g_qp[32 * 2048];
__device__ __align__(16) float g_q[32 * 32 * 576];
__device__ __align__(16) float g_num[32 * 32 * 512];
__device__ float g_den[32 * 32];
__device__ __align__(16) float g_oh[32 * 4096];

__device__ __forceinline__ u64 pk(float a) { u64 r; asm("mov.b64 %0,{%1,%1};" : "=l"(r) : "f"(a)); return r; }
__device__ __forceinline__ void f2(u64& d, u64 a, u64 b) { asm("fma.rn.f32x2 %0,%1,%2,%0;" : "+l"(d) : "l"(a), "l"(b)); }
__device__ __forceinline__ float flo(u64 v) { return __uint_as_float((unsigned)v); }
__device__ __forceinline__ float fhi(u64 v) { return __uint_as_float((unsigned)(v >> 32)); }
__device__ __forceinline__ uint32_t s2u(const void* p) {
    uint32_t a;
    asm("{ .reg .u64 t; cvta.to.shared.u64 t, %1; cvt.u32.u64 %0, t; }" : "=r"(a) : "l"(p));
    return a;
}
__device__ __forceinline__ void mmah(float* d, const uint32_t* a, const uint32_t* b) {
    asm volatile("mma.sync.aligned.m16n8k16.row.col.f32.f16.f16.f32 "
        "{%0,%1,%2,%3}, {%4,%5,%6,%7}, {%8,%9}, {%0,%1,%2,%3};"
        : "+f"(d[0]), "+f"(d[1]), "+f"(d[2]), "+f"(d[3])
        : "r"(a[0]), "r"(a[1]), "r"(a[2]), "r"(a[3]), "r"(b[0]), "r"(b[1]));
}
__device__ __forceinline__ void ldmx4(uint32_t* r, uint32_t a) {
    asm volatile("ldmatrix.sync.aligned.m8n8.x4.shared.b16 {%0,%1,%2,%3}, [%4];"
        : "=r"(r[0]), "=r"(r[1]), "=r"(r[2]), "=r"(r[3]) : "r"(a));
}
__device__ __forceinline__ void ldmx2(uint32_t* r, uint32_t a) {
    asm volatile("ldmatrix.sync.aligned.m8n8.x2.shared.b16 {%0,%1}, [%2];"
        : "=r"(r[0]), "=r"(r[1]) : "r"(a));
}
__device__ __forceinline__ void ldmx2t(uint32_t* r, uint32_t a) {
    asm volatile("ldmatrix.sync.aligned.m8n8.x2.trans.shared.b16 {%0,%1}, [%2];"
        : "=r"(r[0]), "=r"(r[1]) : "r"(a));
}
__device__ __forceinline__ uint2 h2x2(float4 v) {
    __half2 lo = __floats2half2_rn(v.x, v.y), hi = __floats2half2_rn(v.z, v.w);
    uint2 r;
    r.x = *(uint32_t*)&lo; r.y = *(uint32_t*)&hi;
    return r;
}

__global__ void zall(float* out, const float* kc, const float* kpe,
                     float* cK, float* cV, const int* pos,
                     const int* bidx, const int* boff)
{
    int i = blockIdx.x * blockDim.x + threadIdx.x, s = gridDim.x * blockDim.x;
    for (int j = i; j < 131072; j += s) { g_qn[j] = 0.f; g_oh[j] = 0.f; }
    for (int j = i; j < 65536; j += s) g_qp[j] = 0.f;
    for (int j = i; j < 589824; j += s) g_q[j] = 0.f;
    for (int j = i; j < 524288; j += s) g_num[j] = 0.f;
    for (int j = i; j < 1024; j += s) g_den[j] = 0.f;
    for (int j = i; j < 163840; j += s) out[j] = 0.f;
    if (blockIdx.x < 32) {
        int b = blockIdx.x, t = threadIdx.x;
        long long row = (long long)bidx[b] * 128 + boff[b];
        if (t < 32) {
            float p = (float)pos[b];
            float ang = p * exp2f(-(float)t * L2_10K);
            float cv = cosf(ang), sv = sinf(ang);
            float x1 = kpe[b * 64 + t], x2 = kpe[b * 64 + 32 + t];
            cK[row * 64 + t] = x1 * cv - x2 * sv;
            cK[row * 64 + 32 + t] = x2 * cv + x1 * sv;
        }
        for (int j = t; j < 512; j += 256) cV[row * 512 + j] = kc[b * 512 + j];
    }
}

__global__ void gemm32(const float* __restrict__ A, const float* __restrict__ B,
                       float* __restrict__ C, int K, int lda, int ldb, int ldc,
                       int Abs, int Bbs, int Cbs, float alpha)
{
    __shared__ float As[32][33];
    __shared__ __align__(16) float Bs[32][128];
    int bat = blockIdx.z;
    A += (long long)bat * Abs; B += (long long)bat * Bbs; C += (long long)bat * Cbs;
    int kchunk = K / gridDim.y, kbeg = blockIdx.y * kchunk;
    int n0 = blockIdx.x * 128, t = threadIdx.x;
    int tx = t & 31, ty = t >> 5;
    u64 acc[4][2] = {};
    for (int k0 = kbeg; k0 < kbeg + kchunk; k0 += 32) {
        {
            int m = t >> 3, kk = (t & 7) * 4;
            float4 a4 = *(const float4*)(A + (long long)m * lda + k0 + kk);
            As[kk][m] = a4.x; As[kk + 1][m] = a4.y; As[kk + 2][m] = a4.z; As[kk + 3][m] = a4.w;
        }
#pragma unroll
        for (int i = 0; i < 4; i++) {
            int e = t + i * 256, kk = e >> 5, c4 = (e & 31) * 4;
            *(float4*)(&Bs[kk][c4]) = *(const float4*)(B + (long long)(k0 + kk) * ldb + n0 + c4);
        }
        __syncthreads();
#pragma unroll
        for (int kk = 0; kk < 32; kk++) {
            u64 b0 = *(u64*)(&Bs[kk][tx * 4]), b1 = *(u64*)(&Bs[kk][tx * 4 + 2]);
#pragma unroll
            for (int i = 0; i < 4; i++) {
                u64 a = pk(As[kk][ty * 4 + i]);
                f2(acc[i][0], a, b0); f2(acc[i][1], a, b1);
            }
        }
        __syncthreads();
    }
#pragma unroll
    for (int i = 0; i < 4; i++) {
        float* dst = C + (long long)(ty * 4 + i) * ldc + n0 + tx * 4;
        atomicAdd(dst, alpha * flo(acc[i][0])); atomicAdd(dst + 1, alpha * fhi(acc[i][0]));
        atomicAdd(dst + 2, alpha * flo(acc[i][1])); atomicAdd(dst + 3, alpha * fhi(acc[i][1]));
    }
}

__global__ void rope_q(const int* __restrict__ pos) {
    int b = blockIdx.x, t = threadIdx.x;
    float p = (float)pos[b];
#pragma unroll
    for (int r = 0; r < 4; r++) {
        int id = t + r * 256, h = id >> 5, i = id & 31;
        float ang = p * exp2f(-(float)i * L2_10K);
        float cv = cosf(ang), sv = sinf(ang);
        float x1 = g_qp[b * 2048 + h * 64 + i];
        float x2 = g_qp[b * 2048 + h * 64 + 32 + i];
        g_q[(b * 32 + h) * 576 + 512 + i] = (x1 * cv - x2 * sv) * QSCALE;
        g_q[(b * 32 + h) * 576 + 544 + i] = (x2 * cv + x1 * sv) * QSCALE;
    }
}

// smem byte offsets — dual-group layout, 115 KB
#define CHS 584
#define H_Q   0            // q half [32][584] : 37376 (shared)
#define H_CH  37376        // ch half [2][32][584] : 74752
#define H_P   112128       // P half [2][32][40] : 5120
#define F_DEN 117248       // den [32] f32 : 128
#define A_SZ  117376

// grid = 128: CTA = (seq, part); 512 thr = 2 groups x 8 warps; group g does 4 blocks
__global__ void __launch_bounds__(512, 1)
attn_mma(const float* __restrict__ cK, const float* __restrict__ cV,
         const int* __restrict__ blist, const int* __restrict__ bgrp,
         const float* __restrict__ bias)
{
    extern __shared__ char sm[];
    __half* q_h = (__half*)(sm + H_Q);
    float* den_s = (float*)(sm + F_DEN);
    uint32_t sbase = s2u(sm);

    int t = threadIdx.x, lane = t & 31, w = t >> 5;
    int g = w >> 3, wl = w & 7, tg = t & 255;
    __half* ch_h = (__half*)(sm + H_CH + g * 37376);
    __half* p_h = (__half*)(sm + H_P + g * 2560);
    uint32_t qU = sbase + H_Q;
    uint32_t chU = sbase + H_CH + g * 37376;
    uint32_t pU = sbase + H_P + g * 2560;

    int seq = blockIdx.x >> 2, part = blockIdx.x & 3;
    int nbase = seq * 32 + part * 8 + g * 4;
    int b = bgrp[seq * 32];

    long long blks[4];
#pragma unroll
    for (int i = 0; i < 4; i++) blks[i] = blist[nbase + i];

    if (t < 32) den_s[t] = 0.f;
    // stage q -> half (full CTA, once)
    {
        const float* gq = g_q + (long long)b * 18432;
        int row = t >> 4;
#pragma unroll
        for (int j = 0; j < 9; j++) {
            int col = (t & 15) * 4 + j * 64;
            float4 v = *(const float4*)(gq + row * 576 + col);
            *(uint2*)(q_h + row * CHS + col) = h2x2(v);
        }
    }
    __syncthreads();

    int mt = wl & 1, nt = wl >> 1;
    int kr = lane >> 2, lq = lane & 3;
    int l15 = lane & 15, l7 = lane & 7;
    float accav[2][8][4] = {};

    uint32_t aAdr = chU + ((mt * 16 + l15) * CHS + (lane >> 4) * 8) * 2;
    uint32_t bAdr = qU + ((nt * 8 + l7) * CHS + ((lane >> 3) & 1) * 8) * 2;
    uint32_t pA0 = pU + (l15 * 40 + (lane >> 4) * 8) * 2;
    uint32_t pA1 = pU + ((16 + l15) * 40 + (lane >> 4) * 8) * 2;
    uint32_t vB = chU + (l15 * CHS + wl * 64) * 2;

    for (int cc = 0; cc < 16; cc++) {
        int bi = cc >> 2, c = cc & 3;
        const float4* Vg = (const float4*)(cV + blks[bi] * 65536);
        const float4* Kg = (const float4*)(cK + blks[bi] * 8192);
        asm volatile("bar.sync %0, 256;" :: "r"(g + 1) : "memory");   // prev AV done
        // stage kcat chunk -> half (group's 256 threads)
#pragma unroll
        for (int i = 0; i < 18; i++) {
            int idx = tg + i * 256;
            float4 v; int row, cb;
            if (idx < 4096) { row = idx >> 7; cb = (idx & 127) * 4; v = Vg[(c * 32 + row) * 128 + (idx & 127)]; }
            else { int k2 = idx - 4096; row = k2 >> 4; cb = 512 + (k2 & 15) * 4; v = Kg[(c * 32 + row) * 16 + (k2 & 15)]; }
            *(uint2*)(ch_h + row * CHS + cb) = h2x2(v);
        }
        int n = nbase + bi;
        float bb0 = bias[n * 128 + c * 32 + mt * 16 + kr];
        float bb1 = bias[n * 128 + c * 32 + mt * 16 + kr + 8];
        asm volatile("bar.sync %0, 256;" :: "r"(g + 1) : "memory");   // ch ready
        // logits: 36 k16-steps, 2 split accumulators
        float la[2][4] = {};
#pragma unroll
        for (int s = 0; s < 36; s++) {
            uint32_t a[4], bb[2];
            ldmx4(a, aAdr + s * 32);
            ldmx2(bb, bAdr + s * 32);
            mmah(la[s & 1], a, bb);
        }
        float acc[4];
#pragma unroll
        for (int i = 0; i < 4; i++) acc[i] = la[0][i] + la[1][i];
        // exp + P write + den partials
        {
            int key = mt * 16 + kr;
            int h = nt * 8 + lq * 2;
            float p0 = __expf(acc[0] + bb0), p1 = __expf(acc[1] + bb0);
            float p2 = __expf(acc[2] + bb1), p3 = __expf(acc[3] + bb1);
            p_h[h * 40 + key] = __float2half_rn(p0);
            p_h[(h + 1) * 40 + key] = __float2half_rn(p1);
            p_h[h * 40 + key + 8] = __float2half_rn(p2);
            p_h[(h + 1) * 40 + key + 8] = __float2half_rn(p3);
            float d0 = p0 + p2, d1 = p1 + p3;
            d0 += __shfl_xor_sync(~0u, d0, 4); d1 += __shfl_xor_sync(~0u, d1, 4);
            d0 += __shfl_xor_sync(~0u, d0, 8); d1 += __shfl_xor_sync(~0u, d1, 8);
            d0 += __shfl_xor_sync(~0u, d0, 16); d1 += __shfl_xor_sync(~0u, d1, 16);
            if (lane < 4) {
                atomicAdd(&den_s[nt * 8 + lane * 2], d0);
                atomicAdd(&den_s[nt * 8 + lane * 2 + 1], d1);
            }
        }
        asm volatile("bar.sync %0, 256;" :: "r"(g + 1) : "memory");   // P ready
        // AV
#pragma unroll
        for (int s = 0; s < 2; s++) {
            uint32_t a0[4], a1[4];
            ldmx4(a0, pA0 + s * 32);
            ldmx4(a1, pA1 + s * 32);
            uint32_t vBs = vB + s * 16 * CHS * 2;
#pragma unroll
            for (int j = 0; j < 8; j++) {
                uint32_t bb[2];
                ldmx2t(bb, vBs + j * 16);
                mmah(accav[0][j], a0, bb);
                mmah(accav[1][j], a1, bb);
            }
        }
    }
    __syncthreads();
    // epilogue: both groups add their accumulators
#pragma unroll
    for (int m = 0; m < 2; m++)
#pragma unroll
        for (int j = 0; j < 8; j++) {
            int h = m * 16 + kr, l = wl * 64 + j * 8 + lq * 2;
            float* dst = g_num + (long long)(b * 32 + h) * 512 + l;
            atomicAdd(dst, accav[m][j][0]);
            atomicAdd(dst + 1, accav[m][j][1]);
            float* dst2 = g_num + (long long)(b * 32 + h + 8) * 512 + l;
            atomicAdd(dst2, accav[m][j][2]);
            atomicAdd(dst2 + 1, accav[m][j][3]);
        }
    if (t < 32) atomicAdd(&g_den[b * 32 + t], den_s[t]);
}

__global__ void norm_kernel() {
    int i = blockIdx.x * blockDim.x + threadIdx.x;
    g_num[i] = g_num[i] / g_den[i >> 9];
}

extern "C" void kernel_launch(void* const* d_in, const int* in_sizes, int n_in,
                              void* d_out, int out_size)
{
    const float* hid  = (const float*)d_in[0];
    const float* kcn  = (const float*)d_in[1];
    const float* kpe  = (const float*)d_in[2];
    float* cacheK     = (float*)d_in[3];
    float* cacheV     = (float*)d_in[4];
    const float* W_Q  = (const float*)d_in[5];
    const float* W_UK = (const float*)d_in[6];
    const float* W_QR = (const float*)d_in[7];
    const float* W_UV = (const float*)d_in[8];
    const float* W_O  = (const float*)d_in[9];
    const int* pos    = (const int*)d_in[10];
    const int* blist  = (const int*)d_in[11];
    const int* bgrp   = (const int*)d_in[12];
    int o = (in_sizes[13] == 131072) ? 0 : 1;
    const float* bias = (const float*)d_in[13 + o];
    const int* bidx   = (const int*)d_in[14 + o];
    const int* boff   = (const int*)d_in[15 + o];
    float* out = (float*)d_out;

    float *qn, *qp, *q, *num, *oh;
    cudaGetSymbolAddress((void**)&qn, g_qn);
    cudaGetSymbolAddress((void**)&qp, g_qp);
    cudaGetSymbolAddress((void**)&q, g_q);
    cudaGetSymbolAddress((void**)&num, g_num);
    cudaGetSymbolAddress((void**)&oh, g_oh);
    cudaFuncSetAttribute(attn_mma, cudaFuncAttributeMaxDynamicSharedMemorySize, A_SZ);

    zall<<<1024, 256>>>(out, kcn, kpe, cacheK, cacheV, pos, bidx, boff);
    gemm32<<<dim3(32, 4, 1), 256>>>(hid, W_Q, qn, 1536, 1536, 4096, 4096, 0, 0, 0, 1.f);
    gemm32<<<dim3(16, 4, 1), 256>>>(hid, W_QR, qp, 1536, 1536, 2048, 2048, 0, 0, 0, 1.f);
    rope_q<<<32, 256>>>(pos);
    gemm32<<<dim3(4, 1, 32), 256>>>(qn, W_UK, q, 128, 4096, 512, 18432, 128, 65536, 576, QSCALE);
    attn_mma<<<128, 512, A_SZ>>>(cacheK, cacheV, blist, bgrp, bias);
    norm_kernel<<<2048, 256>>>();
    gemm32<<<dim3(1, 4, 32), 256>>>(num, W_UV, oh, 512, 16384, 128, 4096, 512, 65536, 128, 1.f);
    gemm32<<<dim3(40, 8, 1), 256>>>(oh, W_O, out, 4096, 4096, 5120, 5120, 0, 0, 0, 1.f);
}

// round 16
// speedup vs baseline: 1.0738x; 1.0738x over previous
#include <cuda_runtime.h>
#include <cuda_fp16.h>
#include <math.h>
#include <stdint.h>

#define QSCALE 0.07216878364870323f
#define L2_10K 0.41524101186092024f
typedef unsigned long long u64;

__device__ __align__(16) float g_qn[32 * 4096];
__device__ __align__(16) float g_qp[32 * 2048];
__device__ __align__(16) float g_q[32 * 32 * 576];
__device__ __align__(16) float g_num[32 * 32 * 512];
__device__ float g_den[32 * 32];
__device__ __align__(16) float g_oh[32 * 4096];

__device__ __forceinline__ u64 pk(float a) { u64 r; asm("mov.b64 %0,{%1,%1};" : "=l"(r) : "f"(a)); return r; }
__device__ __forceinline__ void f2(u64& d, u64 a, u64 b) { asm("fma.rn.f32x2 %0,%1,%2,%0;" : "+l"(d) : "l"(a), "l"(b)); }
__device__ __forceinline__ float flo(u64 v) { return __uint_as_float((unsigned)v); }
__device__ __forceinline__ float fhi(u64 v) { return __uint_as_float((unsigned)(v >> 32)); }
__device__ __forceinline__ uint32_t s2u(const void* p) {
    uint32_t a;
    asm("{ .reg .u64 t; cvta.to.shared.u64 t, %1; cvt.u32.u64 %0, t; }" : "=r"(a) : "l"(p));
    return a;
}
__device__ __forceinline__ void mmah(float* d, const uint32_t* a, const uint32_t* b) {
    asm volatile("mma.sync.aligned.m16n8k16.row.col.f32.f16.f16.f32 "
        "{%0,%1,%2,%3}, {%4,%5,%6,%7}, {%8,%9}, {%0,%1,%2,%3};"
        : "+f"(d[0]), "+f"(d[1]), "+f"(d[2]), "+f"(d[3])
        : "r"(a[0]), "r"(a[1]), "r"(a[2]), "r"(a[3]), "r"(b[0]), "r"(b[1]));
}
__device__ __forceinline__ void ldmx4(uint32_t* r, uint32_t a) {
    asm volatile("ldmatrix.sync.aligned.m8n8.x4.shared.b16 {%0,%1,%2,%3}, [%4];"
        : "=r"(r[0]), "=r"(r[1]), "=r"(r[2]), "=r"(r[3]) : "r"(a));
}
__device__ __forceinline__ void ldmx2(uint32_t* r, uint32_t a) {
    asm volatile("ldmatrix.sync.aligned.m8n8.x2.shared.b16 {%0,%1}, [%2];"
        : "=r"(r[0]), "=r"(r[1]) : "r"(a));
}
__device__ __forceinline__ void ldmx2t(uint32_t* r, uint32_t a) {
    asm volatile("ldmatrix.sync.aligned.m8n8.x2.trans.shared.b16 {%0,%1}, [%2];"
        : "=r"(r[0]), "=r"(r[1]) : "r"(a));
}
__device__ __forceinline__ uint2 h2x2(float4 v) {
    __half2 lo = __floats2half2_rn(v.x, v.y), hi = __floats2half2_rn(v.z, v.w);
    uint2 r;
    r.x = *(uint32_t*)&lo; r.y = *(uint32_t*)&hi;
    return r;
}

__global__ void zall(float* out, const float* kc, const float* kpe,
                     float* cK, float* cV, const int* pos,
                     const int* bidx, const int* boff)
{
    int i = blockIdx.x * blockDim.x + threadIdx.x, s = gridDim.x * blockDim.x;
    for (int j = i; j < 131072; j += s) { g_qn[j] = 0.f; g_oh[j] = 0.f; }
    for (int j = i; j < 65536; j += s) g_qp[j] = 0.f;
    for (int j = i; j < 589824; j += s) g_q[j] = 0.f;
    for (int j = i; j < 524288; j += s) g_num[j] = 0.f;
    for (int j = i; j < 1024; j += s) g_den[j] = 0.f;
    for (int j = i; j < 163840; j += s) out[j] = 0.f;
    if (blockIdx.x < 32) {
        int b = blockIdx.x, t = threadIdx.x;
        long long row = (long long)bidx[b] * 128 + boff[b];
        if (t < 32) {
            float p = (float)pos[b];
            float ang = p * exp2f(-(float)t * L2_10K);
            float cv = cosf(ang), sv = sinf(ang);
            float x1 = kpe[b * 64 + t], x2 = kpe[b * 64 + 32 + t];
            cK[row * 64 + t] = x1 * cv - x2 * sv;
            cK[row * 64 + 32 + t] = x2 * cv + x1 * sv;
        }
        for (int j = t; j < 512; j += 256) cV[row * 512 + j] = kc[b * 512 + j];
    }
}

__global__ void gemm32(const float* __restrict__ A, const float* __restrict__ B,
                       float* __restrict__ C, int K, int lda, int ldb, int ldc,
                       int Abs, int Bbs, int Cbs, float alpha)
{
    __shared__ float As[32][33];
    __shared__ __align__(16) float Bs[32][128];
    int bat = blockIdx.z;
    A += (long long)bat * Abs; B += (long long)bat * Bbs; C += (long long)bat * Cbs;
    int kchunk = K / gridDim.y, kbeg = blockIdx.y * kchunk;
    int n0 = blockIdx.x * 128, t = threadIdx.x;
    int tx = t & 31, ty = t >> 5;
    u64 acc[4][2] = {};
    for (int k0 = kbeg; k0 < kbeg + kchunk; k0 += 32) {
        {
            int m = t >> 3, kk = (t & 7) * 4;
            float4 a4 = *(const float4*)(A + (long long)m * lda + k0 + kk);
            As[kk][m] = a4.x; As[kk + 1][m] = a4.y; As[kk + 2][m] = a4.z; As[kk + 3][m] = a4.w;
        }
#pragma unroll
        for (int i = 0; i < 4; i++) {
            int e = t + i * 256, kk = e >> 5, c4 = (e & 31) * 4;
            *(float4*)(&Bs[kk][c4]) = *(const float4*)(B + (long long)(k0 + kk) * ldb + n0 + c4);
        }
        __syncthreads();
#pragma unroll
        for (int kk = 0; kk < 32; kk++) {
            u64 b0 = *(u64*)(&Bs[kk][tx * 4]), b1 = *(u64*)(&Bs[kk][tx * 4 + 2]);
#pragma unroll
            for (int i = 0; i < 4; i++) {
                u64 a = pk(As[kk][ty * 4 + i]);
                f2(acc[i][0], a, b0); f2(acc[i][1], a, b1);
            }
        }
        __syncthreads();
    }
#pragma unroll
    for (int i = 0; i < 4; i++) {
        float* dst = C + (long long)(ty * 4 + i) * ldc + n0 + tx * 4;
        atomicAdd(dst, alpha * flo(acc[i][0])); atomicAdd(dst + 1, alpha * fhi(acc[i][0]));
        atomicAdd(dst + 2, alpha * flo(acc[i][1])); atomicAdd(dst + 3, alpha * fhi(acc[i][1]));
    }
}

__global__ void rope_q(const int* __restrict__ pos) {
    int b = blockIdx.x, t = threadIdx.x;
    float p = (float)pos[b];
#pragma unroll
    for (int r = 0; r < 4; r++) {
        int id = t + r * 256, h = id >> 5, i = id & 31;
        float ang = p * exp2f(-(float)i * L2_10K);
        float cv = cosf(ang), sv = sinf(ang);
        float x1 = g_qp[b * 2048 + h * 64 + i];
        float x2 = g_qp[b * 2048 + h * 64 + 32 + i];
        g_q[(b * 32 + h) * 576 + 512 + i] = (x1 * cv - x2 * sv) * QSCALE;
        g_q[(b * 32 + h) * 576 + 544 + i] = (x2 * cv + x1 * sv) * QSCALE;
    }
}

// smem byte offsets — double-buffered fp16 ch, 112 KB
#define CHS 584
#define H_Q   0            // q half [32][584] : 37376
#define H_CH  37376        // ch half [2][32][584] : 74752
#define H_P   112128       // P half [32][40] : 2560
#define F_DEN 114688       // den [32] f32 : 128
#define A_SZ  114816

// grid = 128: CTA = (seq, part); each CTA does 8 consecutive KV blocks (32 chunks)
__global__ void __launch_bounds__(256, 1)
attn_mma(const float* __restrict__ cK, const float* __restrict__ cV,
         const int* __restrict__ blist, const int* __restrict__ bgrp,
         const float* __restrict__ bias)
{
    extern __shared__ char sm[];
    __half* q_h = (__half*)(sm + H_Q);
    float* den_s = (float*)(sm + F_DEN);
    uint32_t sbase = s2u(sm);
    uint32_t qU = sbase + H_Q, pU = sbase + H_P;
    __half* p_h = (__half*)(sm + H_P);

    int t = threadIdx.x, lane = t & 31, w = t >> 5;
    int seq = blockIdx.x >> 2, part = blockIdx.x & 3;
    int nbase = seq * 32 + part * 8;
    int b = bgrp[seq * 32];

    long long blks[8];
#pragma unroll
    for (int i = 0; i < 8; i++) blks[i] = blist[nbase + i];

    if (t < 32) den_s[t] = 0.f;
    // stage q -> half (once)
    {
        const float* gq = g_q + (long long)b * 18432;
        int row = t >> 3;
#pragma unroll
        for (int j = 0; j < 18; j++) {
            int col = (t & 7) * 4 + j * 32;
            float4 v = *(const float4*)(gq + row * 576 + col);
            *(uint2*)(q_h + row * CHS + col) = h2x2(v);
        }
    }

    int mt = w & 1, nt = w >> 1;
    int kr = lane >> 2, lq = lane & 3;
    int l15 = lane & 15, l7 = lane & 7;
    float accav[2][8][4] = {};

    // fixed chunk-staging mapping per thread
    int rowV[18], colh[18];
#pragma unroll
    for (int i = 0; i < 18; i++) {
        int idx = t + i * 256;
        if (idx < 4096) { rowV[i] = idx >> 7; colh[i] = (idx & 127) * 4; }
        else { int k2 = idx - 4096; rowV[i] = k2 >> 4; colh[i] = 512 + (k2 & 15) * 4; }
    }

    uint32_t bAdr = qU + ((nt * 8 + l7) * CHS + ((lane >> 3) & 1) * 8) * 2;
    uint32_t pA0 = pU + (l15 * 40 + (lane >> 4) * 8) * 2;
    uint32_t pA1 = pU + ((16 + l15) * 40 + (lane >> 4) * 8) * 2;

    float4 pre[18];
    // load + store chunk 0 into ch[0]
    {
        const float* Vg = cV + blks[0] * 65536;
        const float* Kg = cK + blks[0] * 8192;
#pragma unroll
        for (int i = 0; i < 18; i++) {
            int idx = t + i * 256;
            const float* src = (idx < 4096) ? (Vg + rowV[i] * 512 + colh[i])
                                            : (Kg + rowV[i] * 64 + colh[i] - 512);
            pre[i] = *(const float4*)src;
        }
        __half* ch0 = (__half*)(sm + H_CH);
#pragma unroll
        for (int i = 0; i < 18; i++)
            *(uint2*)(ch0 + rowV[i] * CHS + colh[i]) = h2x2(pre[i]);
    }
    __syncthreads();

    for (int cc = 0; cc < 32; cc++) {
        int buf = cc & 1;
        uint32_t chU = sbase + H_CH + buf * 37376;
        __half* chN = (__half*)(sm + H_CH + (1 - buf) * 37376);
        uint32_t aAdr = chU + ((mt * 16 + l15) * CHS + (lane >> 4) * 8) * 2;
        uint32_t vB = chU + (l15 * CHS + w * 64) * 2;
        // issue LDGs for chunk cc+1 (land during compute)
        if (cc < 31) {
            int nc = cc + 1;
            const float* Vg = cV + blks[nc >> 2] * 65536;
            const float* Kg = cK + blks[nc >> 2] * 8192;
            int c2 = (nc & 3) * 32;
#pragma unroll
            for (int i = 0; i < 18; i++) {
                int idx = t + i * 256;
                const float* src = (idx < 4096) ? (Vg + (c2 + rowV[i]) * 512 + colh[i])
                                                : (Kg + (c2 + rowV[i]) * 64 + colh[i] - 512);
                pre[i] = *(const float4*)src;
            }
        }
        int n = nbase + (cc >> 2), c = cc & 3;
        float bb0 = bias[n * 128 + c * 32 + mt * 16 + kr];
        float bb1 = bias[n * 128 + c * 32 + mt * 16 + kr + 8];
        // logits: 36 k16-steps, 2 split accumulators
        float la[2][4] = {};
#pragma unroll
        for (int s = 0; s < 36; s++) {
            uint32_t a[4], bb[2];
            ldmx4(a, aAdr + s * 32);
            ldmx2(bb, bAdr + s * 32);
            mmah(la[s & 1], a, bb);
        }
        float acc[4];
#pragma unroll
        for (int i = 0; i < 4; i++) acc[i] = la[0][i] + la[1][i];
        // exp + P write + den partials
        {
            int key = mt * 16 + kr;
            int h = nt * 8 + lq * 2;
            float p0 = __expf(acc[0] + bb0), p1 = __expf(acc[1] + bb0);
            float p2 = __expf(acc[2] + bb1), p3 = __expf(acc[3] + bb1);
            p_h[h * 40 + key] = __float2half_rn(p0);
            p_h[(h + 1) * 40 + key] = __float2half_rn(p1);
            p_h[h * 40 + key + 8] = __float2half_rn(p2);
            p_h[(h + 1) * 40 + key + 8] = __float2half_rn(p3);
            float d0 = p0 + p2, d1 = p1 + p3;
            d0 += __shfl_xor_sync(~0u, d0, 4); d1 += __shfl_xor_sync(~0u, d1, 4);
            d0 += __shfl_xor_sync(~0u, d0, 8); d1 += __shfl_xor_sync(~0u, d1, 8);
            d0 += __shfl_xor_sync(~0u, d0, 16); d1 += __shfl_xor_sync(~0u, d1, 16);
            if (lane < 4) {
                atomicAdd(&den_s[nt * 8 + lane * 2], d0);
                atomicAdd(&den_s[nt * 8 + lane * 2 + 1], d1);
            }
        }
        __syncthreads();                      // P ready
        // AV
#pragma unroll
        for (int s = 0; s < 2; s++) {
            uint32_t a0[4], a1[4];
            ldmx4(a0, pA0 + s * 32);
            ldmx4(a1, pA1 + s * 32);
            uint32_t vBs = vB + s * 16 * CHS * 2;
#pragma unroll
            for (int j = 0; j < 8; j++) {
                uint32_t bb[2];
                ldmx2t(bb, vBs + j * 16);
                mmah(accav[0][j], a0, bb);
                mmah(accav[1][j], a1, bb);
            }
        }
        // commit chunk cc+1 into the other buffer (its old content is free)
        if (cc < 31) {
#pragma unroll
            for (int i = 0; i < 18; i++)
                *(uint2*)(chN + rowV[i] * CHS + colh[i]) = h2x2(pre[i]);
        }
        __syncthreads();                      // AV done (P free) + next ch ready
    }
    // epilogue (once per CTA)
#pragma unroll
    for (int m = 0; m < 2; m++)
#pragma unroll
        for (int j = 0; j < 8; j++) {
            int h = m * 16 + kr, l = w * 64 + j * 8 + lq * 2;
            float* dst = g_num + (long long)(b * 32 + h) * 512 + l;
            atomicAdd(dst, accav[m][j][0]);
            atomicAdd(dst + 1, accav[m][j][1]);
            float* dst2 = g_num + (long long)(b * 32 + h + 8) * 512 + l;
            atomicAdd(dst2, accav[m][j][2]);
            atomicAdd(dst2 + 1, accav[m][j][3]);
        }
    if (t < 32) atomicAdd(&g_den[b * 32 + t], den_s[t]);
}

__global__ void norm_kernel() {
    int i = blockIdx.x * blockDim.x + threadIdx.x;
    g_num[i] = g_num[i] / g_den[i >> 9];
}

extern "C" void kernel_launch(void* const* d_in, const int* in_sizes, int n_in,
                              void* d_out, int out_size)
{
    const float* hid  = (const float*)d_in[0];
    const float* kcn  = (const float*)d_in[1];
    const float* kpe  = (const float*)d_in[2];
    float* cacheK     = (float*)d_in[3];
    float* cacheV     = (float*)d_in[4];
    const float* W_Q  = (const float*)d_in[5];
    const float* W_UK = (const float*)d_in[6];
    const float* W_QR = (const float*)d_in[7];
    const float* W_UV = (const float*)d_in[8];
    const float* W_O  = (const float*)d_in[9];
    const int* pos    = (const int*)d_in[10];
    const int* blist  = (const int*)d_in[11];
    const int* bgrp   = (const int*)d_in[12];
    int o = (in_sizes[13] == 131072) ? 0 : 1;
    const float* bias = (const float*)d_in[13 + o];
    const int* bidx   = (const int*)d_in[14 + o];
    const int* boff   = (const int*)d_in[15 + o];
    float* out = (float*)d_out;

    float *qn, *qp, *q, *num, *oh;
    cudaGetSymbolAddress((void**)&qn, g_qn);
    cudaGetSymbolAddress((void**)&qp, g_qp);
    cudaGetSymbolAddress((void**)&q, g_q);
    cudaGetSymbolAddress((void**)&num, g_num);
    cudaGetSymbolAddress((void**)&oh, g_oh);
    cudaFuncSetAttribute(attn_mma, cudaFuncAttributeMaxDynamicSharedMemorySize, A_SZ);

    zall<<<1024, 256>>>(out, kcn, kpe, cacheK, cacheV, pos, bidx, boff);
    gemm32<<<dim3(32, 4, 1), 256>>>(hid, W_Q, qn, 1536, 1536, 4096, 4096, 0, 0, 0, 1.f);
    gemm32<<<dim3(16, 4, 1), 256>>>(hid, W_QR, qp, 1536, 1536, 2048, 2048, 0, 0, 0, 1.f);
    rope_q<<<32, 256>>>(pos);
    gemm32<<<dim3(4, 1, 32), 256>>>(qn, W_UK, q, 128, 4096, 512, 18432, 128, 65536, 576, QSCALE);
    attn_mma<<<128, 256, A_SZ>>>(cacheK, cacheV, blist, bgrp, bias);
    norm_kernel<<<2048, 256>>>();
    gemm32<<<dim3(1, 4, 32), 256>>>(num, W_UV, oh, 512, 16384, 128, 4096, 512, 65536, 128, 1.f);
    gemm32<<<dim3(40, 8, 1), 256>>>(oh, W_O, out, 4096, 4096, 5120, 5120, 0, 0, 0, 1.f);
}